// round 17
// baseline (speedup 1.0000x reference)
#include <cuda_runtime.h>
#include <cstdint>
#include <cstddef>

#define BATCH 128
#define SEQ   1024
#define DIN   512
#define HID   512

// transposed Wx: g_wt[j][k] = Wx[k][j]  (1MB, L2-resident)
__device__ __align__(16) float g_wt[HID * DIN];
// xp ring: [8 slots][batch][hid] = 2MB, L2-resident
__device__ __align__(16) float g_xr[8 * BATCH * HID];

typedef unsigned long long ull;
static __device__ __forceinline__ ull dup2(float a) {
    ull r; asm("mov.b64 %0, {%1, %1};" : "=l"(r) : "f"(a)); return r;
}
static __device__ __forceinline__ ull pack2(float a, float b) {
    ull r; asm("mov.b64 %0, {%1, %2};" : "=l"(r) : "f"(a), "f"(b)); return r;
}
static __device__ __forceinline__ void unpack2(ull v, float& lo, float& hi) {
    asm("mov.b64 {%0, %1}, %2;" : "=f"(lo), "=f"(hi) : "l"(v));
}
static __device__ __forceinline__ void fma2(ull& acc, ull a, ull b) {
    asm("fma.rn.f32x2 %0, %1, %2, %0;" : "+l"(acc) : "l"(a), "l"(b));
}
static __device__ __forceinline__ ull add2v(ull a, ull b) {
    ull r; asm("add.rn.f32x2 %0, %1, %2;" : "=l"(r) : "l"(a), "l"(b)); return r;
}
static __device__ __forceinline__ float fast_tanh(float x) {
    x = fminf(fmaxf(x, -12.0f), 12.0f);
    const float e = __expf(2.0f * x);
    return __fdividef(e - 1.0f, e + 1.0f);
}

// ============================================================
// Kernel 0: Wx transpose -> g_wt  (~50us)
// ============================================================
__global__ void wt_transpose(const float* __restrict__ Wx)
{
    __shared__ float tile[32][33];
    const int tx = threadIdx.x, ty = threadIdx.y;   // 32 x 8
    const int bx = blockIdx.x, by = blockIdx.y;     // 16 x 16
#pragma unroll
    for (int r = 0; r < 4; r++)
        tile[ty + r * 8][tx] = Wx[(size_t)(by * 32 + ty + r * 8) * HID + bx * 32 + tx];
    __syncthreads();
#pragma unroll
    for (int r = 0; r < 4; r++)
        g_wt[(size_t)(bx * 32 + ty + r * 8) * DIN + by * 32 + tx] = tile[tx][ty + r * 8];
}

// ============================================================
// Kernel B v17: fused scan. R15 h-machinery (verified) + xp
//   production in the ship->wait shadow: x smem-staged, w via
//   batched LDG.128 (L2-resident g_wt), red reused, result to
//   2MB gmem ring (st.cg / ld.cg, same-thread ordering).
// ============================================================
#define WHS_F   (512 * 64)       // 128KB
#define HB_F    (2 * 512 * 8)    //  32KB  hb[buf][k][8rows]
#define RED_U   (4 * 16 * 64)    //  32KB  red[pair][ksl][col]
#define XB_F    (2 * 512 * 8)    //  32KB  xb[buf][k][8rows]
#define SMEM_V17 (WHS_F*4 + HB_F*4 + RED_U*8 + XB_F*4 + 128)
#define SLICE_TXB 2048u

static __device__ __forceinline__ void bar_wait_cta(uint32_t mb, uint32_t parity) {
    uint32_t done;
    asm volatile(
        "{\n\t.reg .pred p;\n\t"
        "mbarrier.try_wait.parity.acquire.cta.shared::cta.b64 p, [%1], %2;\n\t"
        "selp.b32 %0, 1, 0, p;\n\t}"
        : "=r"(done) : "r"(mb), "r"(parity) : "memory");
    if (!done) {
        asm volatile(
            "{\n\t.reg .pred P1;\n\t"
            "W_%=:\n\t"
            "mbarrier.try_wait.parity.acquire.cta.shared::cta.b64 P1, [%0], %1, 0x989680;\n\t"
            "@P1 bra.uni D_%=;\n\t"
            "bra.uni W_%=;\n\t"
            "D_%=:\n\t}"
            :: "r"(mb), "r"(parity) : "memory");
    }
}

__global__ void __launch_bounds__(512, 1) __cluster_dims__(8, 1, 1)
rnn_scan(const float* __restrict__ x,
         const float* __restrict__ Wh,
         const float* __restrict__ bias,
         float* __restrict__ out)
{
    extern __shared__ __align__(16) float smem[];
    float* Whs  = smem;                         // [512][64]
    float* hb   = smem + WHS_F;                 // [2][512][8]
    ull*   red  = (ull*)(hb + HB_F);            // [4][16][64]
    float* xb   = (float*)(red + RED_U);        // [2][512][8]
    ull*   mbar = (ull*)(xb + XB_F);            // [2 buf][8 src]

    const int tid  = threadIdx.x;
    const int rank = blockIdx.x & 7;
    const int cid  = blockIdx.x >> 3;
    const int ksl  = tid >> 5;                  // warp : k-slice
    const int c2   = tid & 31;                  // col-pair
    const int mysrc = ksl >> 1;

    uint32_t mbar_u32, hb_u32;
    asm("{ .reg .u64 t; cvta.to.shared.u64 t, %1; cvt.u32.u64 %0, t; }"
        : "=r"(mbar_u32) : "l"(mbar));
    asm("{ .reg .u64 t; cvta.to.shared.u64 t, %1; cvt.u32.u64 %0, t; }"
        : "=r"(hb_u32) : "l"(hb));

    for (int i = tid; i < 512 * 16; i += 512) {
        const int k = i >> 4, jv = i & 15;
        *(float4*)&Whs[k * 64 + jv * 4] =
            *(const float4*)&Wh[(size_t)k * HID + rank * 64 + jv * 4];
    }
    for (int i = tid; i < HB_F; i += 512) hb[i] = 0.0f;
    if (tid < 16) {
        const uint32_t mb = mbar_u32 + (uint32_t)(tid * 8);
        asm volatile("mbarrier.init.shared.b64 [%0], 1;" :: "r"(mb) : "memory");
        asm volatile("mbarrier.arrive.expect_tx.shared.b64 _, [%0], %1;"
                     :: "r"(mb), "r"(SLICE_TXB) : "memory");
    }

    const int rp = tid >> 6;                    // row-pair 0..3 (tid<256)
    const int c  = tid & 63;                    // col 0..63
    const int jg = rank * 64 + c;
    const int b0 = cid * 8 + 2 * rp;
    const float bv = (tid < 256) ? bias[jg] : 0.0f;

    uint32_t pdst[8], pbar[8];
#pragma unroll
    for (int r = 0; r < 8; r++) {
        const uint32_t la = hb_u32 + (uint32_t)(rank * 2048);
        asm("mapa.shared::cluster.u32 %0, %1, %2;" : "=r"(pdst[r]) : "r"(la), "r"(r));
        const uint32_t lb = mbar_u32 + (uint32_t)(rank * 8);
        asm("mapa.shared::cluster.u32 %0, %1, %2;" : "=r"(pbar[r]) : "r"(lb), "r"(r));
    }

    // fused-gemm constants
    const float* w0p = g_wt + (size_t)(rank * 64 + 2 * c2) * DIN + ksl * 32;  // col0 slice
    const float* w1p = w0p + DIN;                                            // col1 slice
    const float* xbase = x + (size_t)(cid * 8) * SEQ * DIN;                   // batch base

    asm volatile("barrier.cluster.arrive.aligned;" ::: "memory");
    asm volatile("barrier.cluster.wait.aligned;"   ::: "memory");

    // ---------- helpers ----------
#define STAGE_LD(S, XR) do {                                              \
        const float* xs_ = xbase + (size_t)(S) * DIN + tid;              \
        _Pragma("unroll")                                                \
        for (int b_ = 0; b_ < 8; b_++)                                   \
            (XR)[b_] = xs_[(size_t)b_ * SEQ * DIN];                      \
    } while (0)
#define STAGE_ST(BUF, XR) do {                                            \
        float4 f0_, f1_;                                                 \
        f0_.x=(XR)[0]; f0_.y=(XR)[1]; f0_.z=(XR)[2]; f0_.w=(XR)[3];      \
        f1_.x=(XR)[4]; f1_.y=(XR)[5]; f1_.z=(XR)[6]; f1_.w=(XR)[7];      \
        *(float4*)&xb[(BUF) * 4096 + tid * 8]     = f0_;                 \
        *(float4*)&xb[(BUF) * 4096 + tid * 8 + 4] = f1_;                 \
    } while (0)
    // compute one column's 32-k partials from xb[BUF] using 8 preloaded float4 w regs
#define GCOL(WR, XKP, C0, C1, C2, C3) do {                                \
        _Pragma("unroll")                                                \
        for (int q_ = 0; q_ < 8; q_++) {                                 \
            const float wv_[4] = {(WR)[q_].x,(WR)[q_].y,(WR)[q_].z,(WR)[q_].w}; \
            _Pragma("unroll")                                            \
            for (int j_ = 0; j_ < 4; j_++) {                             \
                const int kk_ = q_ * 4 + j_;                             \
                const ulonglong2 x01 = *(const ulonglong2*)((XKP) + kk_ * 4);     \
                const ulonglong2 x23 = *(const ulonglong2*)((XKP) + kk_ * 4 + 2); \
                const ull wd_ = dup2(wv_[j_]);                           \
                fma2(C0, x01.x, wd_); fma2(C1, x01.y, wd_);              \
                fma2(C2, x23.x, wd_); fma2(C3, x23.y, wd_);              \
            }                                                            \
        }                                                                \
    } while (0)
#define GCHUNK(BUF) do {                                                  \
        const ull* xkp_ = (const ull*)(xb + (BUF) * 4096) + (size_t)ksl * 32 * 4; \
        float4 wr_[8];                                                  \
        _Pragma("unroll")                                                \
        for (int i_ = 0; i_ < 8; i_++) wr_[i_] = *(const float4*)(w0p + i_ * 4); \
        ull g0_=0, g1_=0, g2_=0, g3_=0;                                  \
        GCOL(wr_, xkp_, g0_, g1_, g2_, g3_);                             \
        red[(0 * 16 + ksl) * 64 + 2 * c2] = g0_;                         \
        red[(1 * 16 + ksl) * 64 + 2 * c2] = g1_;                         \
        red[(2 * 16 + ksl) * 64 + 2 * c2] = g2_;                         \
        red[(3 * 16 + ksl) * 64 + 2 * c2] = g3_;                         \
        _Pragma("unroll")                                                \
        for (int i_ = 0; i_ < 8; i_++) wr_[i_] = *(const float4*)(w1p + i_ * 4); \
        ull h0_=0, h1_=0, h2_=0, h3_=0;                                  \
        GCOL(wr_, xkp_, h0_, h1_, h2_, h3_);                             \
        red[(0 * 16 + ksl) * 64 + 2 * c2 + 1] = h0_;                     \
        red[(1 * 16 + ksl) * 64 + 2 * c2 + 1] = h1_;                     \
        red[(2 * 16 + ksl) * 64 + 2 * c2 + 1] = h2_;                     \
        red[(3 * 16 + ksl) * 64 + 2 * c2 + 1] = h3_;                     \
    } while (0)
#define GREDUCE(SLOT) do {                                                \
        const ull* rb_ = red + (size_t)rp * (16 * 64) + c;               \
        ull s_[8];                                                       \
        _Pragma("unroll")                                                \
        for (int i_ = 0; i_ < 8; i_++)                                   \
            s_[i_] = add2v(rb_[(size_t)(2 * i_) * 64],                   \
                           rb_[(size_t)(2 * i_ + 1) * 64]);              \
        s_[0]=add2v(s_[0],s_[1]); s_[2]=add2v(s_[2],s_[3]);              \
        s_[4]=add2v(s_[4],s_[5]); s_[6]=add2v(s_[6],s_[7]);              \
        s_[0]=add2v(s_[0],s_[2]); s_[4]=add2v(s_[4],s_[6]);              \
        s_[0]=add2v(s_[0],s_[4]);                                        \
        float lo_, hi_; unpack2(s_[0], lo_, hi_);                        \
        float* o_ = g_xr + (size_t)(SLOT) * (BATCH * HID) + (size_t)b0 * HID + jg; \
        __stcg(o_, lo_ + bv);                                            \
        __stcg(o_ + HID, hi_ + bv);                                      \
    } while (0)

    // ---------- prologue: xp[0], xp[1]; xb <- x[2], x[3] ----------
    {
        float xr[8];
        STAGE_LD(0, xr); STAGE_ST(0, xr);
        __syncthreads();
        GCHUNK(0);
        __syncthreads();
        if (tid < 256) GREDUCE(0);
        STAGE_LD(1, xr); STAGE_ST(1, xr);
        __syncthreads();
        GCHUNK(1);
        __syncthreads();
        if (tid < 256) GREDUCE(1);
        STAGE_LD(2, xr); STAGE_ST(0, xr);
        STAGE_LD(3, xr); STAGE_ST(1, xr);
        __syncthreads();
    }

    const float* wp = Whs + (ksl * 32) * 64 + 2 * c2;
    const uint32_t mywait = mbar_u32 + (uint32_t)(mysrc * 8);

    for (int t = 0; t < SEQ; t++) {
        const int cur = t & 1, nb = cur ^ 1;
        const bool do_chunk  = (t <= SEQ - 3);   // produce xp[t+2]
        const bool do_refill = (t <= SEQ - 5);   // stage x[t+4]

        // xp[t] prefetch (ld.cg, written by this same thread at t-2)
        float xp0 = 0.f, xp1 = 0.f;
        if (tid < 256) {
            const float* xs_ = g_xr + (size_t)(t & 7) * (BATCH * HID)
                             + (size_t)b0 * HID + jg;
            xp0 = __ldcg(xs_);
            xp1 = __ldcg(xs_ + HID);
        }
        // early-issue x[t+4] loads (lands during wait + kloop)
        float xr[8];
        if (do_refill) STAGE_LD(t + 4, xr);

        if (t > 0) {
            const uint32_t parity = (uint32_t)(((t - 1) >> 1) & 1);
            const uint32_t mb = mywait + (uint32_t)(cur * 64);
            bar_wait_cta(mb, parity);
            if ((ksl & 1) == 0 && c2 == 0) {
                asm volatile("mbarrier.arrive.expect_tx.shared.b64 _, [%0], %1;"
                             :: "r"(mb), "r"(SLICE_TXB) : "memory");
            }
        }

        // ---- h k-loop ----
        const ull* hc = (const ull*)(hb + cur * 4096) + (size_t)ksl * 32 * 4;
        ull a00=0, a01=0, a10=0, a11=0, a20=0, a21=0, a30=0, a31=0;
#pragma unroll 8
        for (int kk = 0; kk < 32; kk++) {
            const float2 w = *(const float2*)(wp + kk * 64);
            const ulonglong2 h01 = *(const ulonglong2*)(hc + kk * 4);
            const ulonglong2 h23 = *(const ulonglong2*)(hc + kk * 4 + 2);
            const ull w0 = dup2(w.x), w1 = dup2(w.y);
            fma2(a00, h01.x, w0); fma2(a01, h01.y, w0);
            fma2(a10, h23.x, w0); fma2(a11, h23.y, w0);
            fma2(a20, h01.x, w1); fma2(a21, h01.y, w1);
            fma2(a30, h23.x, w1); fma2(a31, h23.y, w1);
        }
        {   // h partials -> red[pair][ksl][col]
            ulonglong2 v;
            v.x = a00; v.y = a20;
            *(ulonglong2*)&red[(0 * 16 + ksl) * 64 + 2 * c2] = v;
            v.x = a01; v.y = a21;
            *(ulonglong2*)&red[(1 * 16 + ksl) * 64 + 2 * c2] = v;
            v.x = a10; v.y = a30;
            *(ulonglong2*)&red[(2 * 16 + ksl) * 64 + 2 * c2] = v;
            v.x = a11; v.y = a31;
            *(ulonglong2*)&red[(3 * 16 + ksl) * 64 + 2 * c2] = v;
        }
        __syncthreads();   // sync1

        if (tid < 256) {   // h reduce + tanh -> direct hb[nb] write (R10-style)
            const ull* rbase = red + (size_t)rp * (16 * 64) + c;
            ull s[8];
#pragma unroll
            for (int i = 0; i < 8; i++)
                s[i] = add2v(rbase[(size_t)(2 * i) * 64], rbase[(size_t)(2 * i + 1) * 64]);
            s[0] = add2v(s[0], s[1]); s[2] = add2v(s[2], s[3]);
            s[4] = add2v(s[4], s[5]); s[6] = add2v(s[6], s[7]);
            s[0] = add2v(s[0], s[2]); s[4] = add2v(s[4], s[6]);
            s[0] = add2v(s[0], s[4]);
            float lo, hi; unpack2(s[0], lo, hi);
            const float v0 = fast_tanh(lo + xp0);
            const float v1 = fast_tanh(hi + xp1);
            *(ull*)&hb[(size_t)nb * 4096 + jg * 8 + 2 * rp] = pack2(v0, v1);
        }
        __syncthreads();   // sync2 (hb[nb] slice complete, red free)

        if (tid == 0) {    // ship h(t+1) from hb[nb] rank slice
            asm volatile("fence.proxy.async.shared::cta;" ::: "memory");
            const uint32_t src  = hb_u32 + (uint32_t)(nb * 16384 + rank * 2048);
            const uint32_t doff = (uint32_t)(nb * 16384);
            const uint32_t boff = (uint32_t)(nb * 64);
#pragma unroll
            for (int r = 0; r < 8; r++) {
                asm volatile(
                    "cp.async.bulk.shared::cluster.shared::cta.mbarrier::complete_tx::bytes "
                    "[%0], [%1], %2, [%3];"
                    :: "r"(pdst[r] + doff), "r"(src), "r"(SLICE_TXB), "r"(pbar[r] + boff)
                    : "memory");
            }
        }

        // ---- fused gemm chunk: xp[t+2] partials (in the ship shadow) ----
        if (do_chunk) GCHUNK(t & 1);
        __syncthreads();   // sync3

        if (do_chunk && tid < 256) GREDUCE((t + 2) & 7);
        if (do_refill) STAGE_ST(t & 1, xr);     // xb[t&1] <- x[t+4]
        __syncthreads();   // sync4 (red + xb settled)
    }

    bar_wait_cta(mywait, 1u);
    __syncthreads();
    if (tid < 256) {
        const float2 hv = *(const float2*)&hb[jg * 8 + 2 * rp];
        out[(size_t)b0 * HID + jg]       = hv.x;
        out[(size_t)(b0 + 1) * HID + jg] = hv.y;
    }

    asm volatile("barrier.cluster.arrive.aligned;" ::: "memory");
    asm volatile("barrier.cluster.wait.aligned;"   ::: "memory");
#undef STAGE_LD
#undef STAGE_ST
#undef GCOL
#undef GCHUNK
#undef GREDUCE
}

// ============================================================
extern "C" void kernel_launch(void* const* d_in, const int* in_sizes, int n_in,
                              void* d_out, int out_size)
{
    (void)in_sizes; (void)n_in; (void)out_size;
    const float* x    = (const float*)d_in[0];
    const float* Wx   = (const float*)d_in[1];
    const float* Wh   = (const float*)d_in[2];
    const float* bias = (const float*)d_in[3];
    float* out = (float*)d_out;

    cudaFuncSetAttribute(rnn_scan, cudaFuncAttributeMaxDynamicSharedMemorySize, SMEM_V17);

    wt_transpose<<<dim3(16, 16), dim3(32, 8)>>>(Wx);
    rnn_scan<<<128, 512, SMEM_V17>>>(x, Wh, bias, out);
}